// round 15
// baseline (speedup 1.0000x reference)
#include <cuda_runtime.h>
#include <math.h>
#include <stdint.h>

#define Bb   128
#define Hh   1024
#define HH2  512
#define Vv   32000
#define Ll   2
#define MAXW 21
#define WSZF 10.0f
#define NT2  500          // fc2 softmax partial slots (250 tiles x 2 warp-cols)

// output layout (concatenated tuple: y, o2, h_new, c_new, a)
#define Y_OFF  0
#define O2_OFF (Bb*Vv)
#define H_OFF  (O2_OFF + Bb*Hh)
#define C_OFF  (H_OFF + Ll*Bb*Hh)
#define A_OFF  (C_OFF + Ll*Bb*Hh)

#define SLAB (Bb*4*Hh)   // one gates partial slab (128 x 4096)

// scratch (device globals — no allocation allowed)
__device__ float g_gates[4*Bb*4*Hh];    // L0 slabs; later fc1 partials
__device__ float g_gates2[6*Bb*4*Hh];   // L1 slabs; later attn proj partials
__device__ float g_pb[Bb];
__device__ float g_ctx[Bb*Hh];
__device__ float g_pm[Bb*NT2];
__device__ float g_ps[Bb*NT2];

__device__ __forceinline__ float sigm(float x) { return 1.0f / (1.0f + expf(-x)); }

// ---------------------------------------------------------------------------
// async-copy / mma helpers
__device__ __forceinline__ void cp16(uint32_t dst, const float* src) {
    asm volatile("cp.async.cg.shared.global [%0], [%1], 16;"
                 :: "r"(dst), "l"(__cvta_generic_to_global(src)));
}
__device__ __forceinline__ void ldm_x4(uint32_t* r, uint32_t addr) {
    asm volatile("ldmatrix.sync.aligned.m8n8.x4.shared.b16 {%0,%1,%2,%3}, [%4];"
                 : "=r"(r[0]), "=r"(r[1]), "=r"(r[2]), "=r"(r[3]) : "r"(addr));
}
__device__ __forceinline__ void cvt_tf32(uint32_t& x) {
    asm volatile("cvt.rna.tf32.f32 %0, %0;" : "+r"(x));
}
__device__ __forceinline__ void mma_tf32(float* d, const uint32_t* a, const uint32_t* b) {
    asm volatile("mma.sync.aligned.m16n8k8.row.col.f32.tf32.tf32.f32 "
                 "{%0,%1,%2,%3}, {%4,%5,%6,%7}, {%8,%9}, {%0,%1,%2,%3};"
                 : "+f"(d[0]), "+f"(d[1]), "+f"(d[2]), "+f"(d[3])
                 : "r"(a[0]), "r"(a[1]), "r"(a[2]), "r"(a[3]),
                   "r"(b[0]), "r"(b[1]));
}

// swizzled byte offset of 16B chunk (row stride 128B, 8 chunks/row)
__device__ __forceinline__ uint32_t swz(int row, int chunk) {
    return (uint32_t)(row * 128 + ((chunk ^ (row & 7)) << 4));
}

// online (m,s) merge
__device__ __forceinline__ void msmerge(float& m, float& s, float om, float os) {
    float nm = fmaxf(m, om);
    s = s * __expf(m - nm) + os * __expf(om - nm);
    m = nm;
}

// ---------------------------------------------------------------------------
// Stage a K-chunk of 32 fp32 cols: A[128 rows] (optionally word-indirect rows),
// W[BN rows] -> swizzled SMEM.
template<int BN, int NW>
__device__ __forceinline__ void g_load(
    uint32_t abase, const float* __restrict__ A, const int* __restrict__ word,
    const float* __restrict__ W, int ldA, int ldW, int kOff,
    int kb, int n0, int tid)
{
    constexpr int THREADS = NW * 32;
    uint32_t bbase = abase + 128 * 128;
    #pragma unroll
    for (int i = 0; i < 1024 / THREADS; i++) {          // A: 128 rows x 8 chunks
        int idx = tid + i * THREADS;
        int r = idx >> 3, c = idx & 7;
        long rowoff = word ? (long)word[r] * ldA : (long)r * ldA;
        cp16(abase + swz(r, c), A + rowoff + kOff + kb + c * 4);
    }
    #pragma unroll
    for (int i = 0; i < BN * 8 / THREADS; i++) {        // B: BN rows x 8 chunks
        int idx = tid + i * THREADS;
        int r = idx >> 3, c = idx & 7;
        cp16(bbase + swz(r, c), W + (long)(n0 + r) * ldW + kb + c * 4);
    }
}

// ---------------------------------------------------------------------------
// Core tf32 mma GEMM. ACT: 0 = bias, 1 = bias+tanh, 2 = raw.
// SMX: emit per-row (max, sumexp) partials for fused log-softmax
// (slot = tile + wn so multiple N-warps don't collide).
template<int BN, int NW, int WN, int NST, int ACT, int SMX>
__device__ __forceinline__ void gemm_core(
    const float* __restrict__ A, const int* __restrict__ word,
    const float* __restrict__ W, int ldA, int ldW, int kOff, int kLen,
    const float* __restrict__ bias, float* __restrict__ C, int N, int n0, char* sm,
    float* __restrict__ Pm, float* __restrict__ Ps, int tile, int nTiles)
{
    constexpr int STAGE = (128 + BN) * 128;
    constexpr int WARPN = BN / WN, NT = WARPN / 8;
    constexpr int WM = NW / WN, WTM = 128 / WM, MT = WTM / 16;

    uint32_t smb = (uint32_t)__cvta_generic_to_shared(sm);
    int tid = threadIdx.x, lane = tid & 31, w = tid >> 5;
    int wm = w / WN, wn = w % WN;
    int NITER = kLen / 32;

    float acc[MT][NT][4] = {};

    #pragma unroll
    for (int s = 0; s < NST; s++) {
        if (s < NITER)
            g_load<BN, NW>(smb + s * STAGE, A, word, W, ldA, ldW, kOff, s * 32, n0, tid);
        asm volatile("cp.async.commit_group;" ::: "memory");
    }

    int a_lrow = lane & 15, a_lsel = lane >> 4;
    int b_lrow = (lane & 7) + ((lane >> 4) << 3);
    int b_lsel = (lane >> 3) & 1;

    for (int it = 0; it < NITER; it++) {
        asm volatile("cp.async.wait_group %0;" :: "n"(NST - 1) : "memory");
        __syncthreads();

        uint32_t abase = smb + (it % NST) * STAGE;
        uint32_t bbase = abase + 128 * 128;
        #pragma unroll
        for (int ks = 0; ks < 4; ks++) {
            int cb = 2 * ks;
            uint32_t a[MT][4], b[NT][2];
            #pragma unroll
            for (int mt = 0; mt < MT; mt++) {
                int row = wm * WTM + mt * 16 + a_lrow;
                ldm_x4(a[mt], abase + (uint32_t)(row * 128 +
                       (((cb + a_lsel) ^ (a_lrow & 7)) << 4)));
            }
            #pragma unroll
            for (int j = 0; j < NT / 2; j++) {
                int row = wn * WARPN + j * 16 + b_lrow;
                uint32_t r4[4];
                ldm_x4(r4, bbase + (uint32_t)(row * 128 +
                       (((cb + b_lsel) ^ (b_lrow & 7)) << 4)));
                b[j*2][0] = r4[0]; b[j*2][1] = r4[1];
                b[j*2+1][0] = r4[2]; b[j*2+1][1] = r4[3];
            }
            #pragma unroll
            for (int mt = 0; mt < MT; mt++)
                #pragma unroll
                for (int q = 0; q < 4; q++) cvt_tf32(a[mt][q]);
            #pragma unroll
            for (int nt = 0; nt < NT; nt++) { cvt_tf32(b[nt][0]); cvt_tf32(b[nt][1]); }
            #pragma unroll
            for (int mt = 0; mt < MT; mt++)
                #pragma unroll
                for (int nt = 0; nt < NT; nt++)
                    mma_tf32(acc[mt][nt], a[mt], b[nt]);
        }
        __syncthreads();
        if (it + NST < NITER)
            g_load<BN, NW>(smb + (it % NST) * STAGE, A, word, W, ldA, ldW, kOff,
                           (it + NST) * 32, n0, tid);
        asm volatile("cp.async.commit_group;" ::: "memory");
    }

    // epilogue
    #pragma unroll
    for (int mt = 0; mt < MT; mt++) {
        int mrow = wm * WTM + mt * 16 + (lane >> 2);
        float em0 = -1e30f, es0 = 0.0f, em1 = -1e30f, es1 = 0.0f;
        #pragma unroll
        for (int nt = 0; nt < NT; nt++) {
            int n = n0 + wn * WARPN + nt * 8 + (lane & 3) * 2;
            float b0a = 0.0f, b0b = 0.0f;
            if (ACT != 2) { b0a = bias[n]; b0b = bias[n + 1]; }
            float v0 = acc[mt][nt][0] + b0a;
            float v1 = acc[mt][nt][1] + b0b;
            float v2 = acc[mt][nt][2] + b0a;
            float v3 = acc[mt][nt][3] + b0b;
            if (ACT == 1) { v0 = tanhf(v0); v1 = tanhf(v1); v2 = tanhf(v2); v3 = tanhf(v3); }
            if (SMX) {
                float nm = fmaxf(em0, fmaxf(v0, v1));
                es0 = es0 * __expf(em0 - nm) + __expf(v0 - nm) + __expf(v1 - nm);
                em0 = nm;
                nm = fmaxf(em1, fmaxf(v2, v3));
                es1 = es1 * __expf(em1 - nm) + __expf(v2 - nm) + __expf(v3 - nm);
                em1 = nm;
            }
            *(float2*)(C + (long)mrow * N + n)       = make_float2(v0, v1);
            *(float2*)(C + (long)(mrow + 8) * N + n) = make_float2(v2, v3);
        }
        if (SMX) {
            #pragma unroll
            for (int o = 1; o <= 2; o <<= 1) {
                msmerge(em0, es0, __shfl_xor_sync(~0u, em0, o), __shfl_xor_sync(~0u, es0, o));
                msmerge(em1, es1, __shfl_xor_sync(~0u, em1, o), __shfl_xor_sync(~0u, es1, o));
            }
            if ((lane & 3) == 0) {
                int slot = tile + wn;
                Pm[(long)mrow * nTiles + slot]       = em0;
                Ps[(long)mrow * nTiles + slot]       = es0;
                Pm[(long)(mrow + 8) * nTiles + slot] = em1;
                Ps[(long)(mrow + 8) * nTiles + slot] = es1;
            }
        }
    }
}

// ---------------------------------------------------------------------------
// Mega gates: job0 = emb[word]@Wih0 (sk2), job1 = h0[0]@Whh0 (sk2),
// job2 = h0[1]@Whh1 (sk2). BN=64. grid = 384.
__global__ void __launch_bounds__(128, 4) k_mega_gates(
    const float* __restrict__ emb, const int* __restrict__ word,
    const float* __restrict__ h00, const float* __restrict__ Wih0,
    const float* __restrict__ Whh0,
    const float* __restrict__ h01, const float* __restrict__ Whh1,
    float* __restrict__ G0, float* __restrict__ G1)
{
    extern __shared__ char sm[];
    int job = blockIdx.x >> 7;
    int r = blockIdx.x & 127;
    int tile = r >> 1, ks = r & 1;
    const float* A; const int* wd = nullptr; const float* W; float* C; int kOff = 0;
    if (job == 0)      { A = emb;             wd = word; kOff = ks * 512;
                         W = Wih0 + ks * 512; C = G0 + (long)ks * SLAB; }
    else if (job == 1) { A = h00 + ks * 512;  W = Whh0 + ks * 512;
                         C = G0 + (long)(2 + ks) * SLAB; }
    else               { A = h01 + ks * 512;  W = Whh1 + ks * 512;
                         C = G1 + (long)ks * SLAB; }
    gemm_core<64, 4, 1, 2, 2, 0>(A, wd, W, Hh, Hh, kOff, 512, nullptr,
                                 C, 4 * Hh, tile * 64, sm, nullptr, nullptr, 0, 0);
}

// Layer-1 x-part: h_l0 @ Wih1 (split-K4). BN=64. grid = 256.
__global__ void __launch_bounds__(128, 4) k_gates_x1(
    const float* __restrict__ hl0, const float* __restrict__ Wih1,
    float* __restrict__ G1)
{
    extern __shared__ char sm[];
    int tile = blockIdx.x >> 2, ks = blockIdx.x & 3;
    gemm_core<64, 4, 1, 2, 2, 0>(hl0 + ks * 256, nullptr, Wih1 + ks * 256,
                                 Hh, Hh, 0, 256, nullptr,
                                 G1 + (long)(2 + ks) * SLAB, 4 * Hh, tile * 64, sm,
                                 nullptr, nullptr, 0, 0);
}

// attn proj split-K=4 (K quarters of 256). BN=32. grid = 64. partials g_gates2.
__global__ void __launch_bounds__(128, 4) k_proj_sk4(
    const float* __restrict__ hout, const float* __restrict__ aw1,
    float* __restrict__ P)
{
    extern __shared__ char sm[];
    int ks = blockIdx.x & 3, tile = blockIdx.x >> 2;
    gemm_core<32, 4, 1, 2, 2, 0>(hout + ks * 256, nullptr, aw1 + ks * 256,
                                 Hh, Hh, 0, 256, nullptr,
                                 P + (long)ks * 128 * HH2, HH2, tile * 32, sm,
                                 nullptr, nullptr, 0, 0);
}

// fc1 hout-half: K-quarters 2,3 -> slabs 2,3. BN=32. grid = 64. (side stream)
__global__ void __launch_bounds__(128, 4) k_fc1_hout(
    const float* __restrict__ hout, const float* __restrict__ f1w,
    float* __restrict__ P)
{
    extern __shared__ char sm[];
    int ks = 2 + (blockIdx.x & 1), tile = blockIdx.x >> 1;
    gemm_core<32, 4, 1, 2, 2, 0>(hout + (ks - 2) * 512, nullptr, f1w + ks * 512,
                                 Hh, 2 * Hh, 0, 512, nullptr,
                                 P + (long)ks * 128 * Hh, Hh, tile * 32, sm,
                                 nullptr, nullptr, 0, 0);
}

// fc1 ctx-half: K-quarters 0,1 -> slabs 0,1. BN=32. grid = 64.
__global__ void __launch_bounds__(128, 4) k_fc1_ctx(
    const float* __restrict__ ctx, const float* __restrict__ f1w,
    float* __restrict__ P)
{
    extern __shared__ char sm[];
    int ks = blockIdx.x & 1, tile = blockIdx.x >> 1;
    gemm_core<32, 4, 1, 2, 2, 0>(ctx + ks * 512, nullptr, f1w + ks * 512,
                                 Hh, 2 * Hh, 0, 512, nullptr,
                                 P + (long)ks * 128 * Hh, Hh, tile * 32, sm,
                                 nullptr, nullptr, 0, 0);
}

// fc2: BN=128, 256 threads, WN=2, NST=3, fused softmax partials. grid = 250.
__global__ void __launch_bounds__(256, 2) k_fc2(
    const float* __restrict__ o2, const float* __restrict__ f2w,
    const float* __restrict__ f2b, float* __restrict__ y,
    float* __restrict__ Pm, float* __restrict__ Ps)
{
    extern __shared__ char sm[];
    gemm_core<128, 8, 2, 3, 0, 1>(o2, nullptr, f2w, Hh, Hh, 0, Hh, f2b,
                                  y, Vv, blockIdx.x * 128, sm, Pm, Ps,
                                  blockIdx.x * 2, NT2);
}

// ---------------------------------------------------------------------------
// LSTM cell 0 (scalar): gates = x-ks0 + x-ks1 + h-ks0 + h-ks1 + bih + bhh
__global__ void k_lstm_cell(const float* __restrict__ p0, const float* __restrict__ p1,
                            const float* __restrict__ bi, const float* __restrict__ bh,
                            const float* __restrict__ c_prev,
                            float* __restrict__ c_out, float* __restrict__ h_out) {
    int i = blockIdx.x * 256 + threadIdx.x;   // B*H
    int b = i >> 10, h = i & 1023;
    long base = (long)b * 4 * Hh + h;
    float gate[4];
    #pragma unroll
    for (int gi = 0; gi < 4; gi++) {
        long off = base + gi * Hh;
        gate[gi] = p0[off] + p0[SLAB + off] + p1[off] + p1[SLAB + off]
                 + bi[gi * Hh + h] + bh[gi * Hh + h];
    }
    float cp = c_prev[i];
    float c = sigm(gate[1]) * cp + sigm(gate[0]) * tanhf(gate[2]);
    c_out[i] = c;
    h_out[i] = sigm(gate[3]) * tanhf(c);
}

// LSTM cell 1 (scalar): gates = sum of 6 slabs + bih + bhh
__global__ void k_lstm_cell6(const float* __restrict__ P,
                             const float* __restrict__ bi, const float* __restrict__ bh,
                             const float* __restrict__ c_prev,
                             float* __restrict__ c_out, float* __restrict__ h_out) {
    int i = blockIdx.x * 256 + threadIdx.x;   // B*H
    int b = i >> 10, h = i & 1023;
    long base = (long)b * 4 * Hh + h;
    float gate[4];
    #pragma unroll
    for (int gi = 0; gi < 4; gi++) {
        long off = base + gi * Hh;
        float v = P[off];
        #pragma unroll
        for (int sl = 1; sl < 6; sl++) v += P[(long)sl * SLAB + off];
        gate[gi] = v + bi[gi * Hh + h] + bh[gi * Hh + h];
    }
    float cp = c_prev[i];
    float c = sigm(gate[1]) * cp + sigm(gate[0]) * tanhf(gate[2]);
    c_out[i] = c;
    h_out[i] = sigm(gate[3]) * tanhf(c);
}

// ---------------------------------------------------------------------------
// 4-partial combine with tanh (fc1), scalar
__global__ void k_comb4_tanh(const float* __restrict__ P, const float* __restrict__ bias,
                             float* __restrict__ out, int N) {
    int i = blockIdx.x * 256 + threadIdx.x;   // over 128*N
    long s = (long)128 * N;
    int h = i % N;
    out[i] = tanhf(P[i] + P[s + i] + P[2 * s + i] + P[3 * s + i] + bias[h]);
}

// ---------------------------------------------------------------------------
// Fused attn position: combine 4 proj partials + bias, tanh, dot w2, sigmoid -> pb
__global__ void k_attnpos(const float* __restrict__ P, const float* __restrict__ ab1,
                          const float* __restrict__ w2, const float* __restrict__ b2,
                          int S) {
    int b = blockIdx.x, tid = threadIdx.x;
    long s = (long)128 * HH2;
    long row = (long)b * HH2;
    __shared__ float red[4];
    float acc = 0.0f;
    #pragma unroll
    for (int jj = 0; jj < HH2 / 128; jj++) {
        int j = tid + jj * 128;
        float v = P[row + j] + P[s + row + j] + P[2 * s + row + j] + P[3 * s + row + j]
                + ab1[j];
        acc += tanhf(v) * w2[j];
    }
    #pragma unroll
    for (int o = 16; o > 0; o >>= 1) acc += __shfl_xor_sync(~0u, acc, o);
    if ((tid & 31) == 0) red[tid >> 5] = acc;
    __syncthreads();
    if (tid == 0)
        g_pb[b] = (float)S * sigm(red[0] + red[1] + red[2] + red[3] + b2[0]);
}

// ---------------------------------------------------------------------------
// Windowed attention (512 threads): scores, softmax*gauss, a, ctx
__global__ void k_attn_ctx(const float* __restrict__ hout, const float* __restrict__ enc,
                           int S, float* __restrict__ a_out) {
    int b = blockIdx.x, tid = threadIdx.x;
    int warp = tid >> 5, lane = tid & 31;
    float pb = g_pb[b];
    int ws = (int)rintf(fmaxf(pb - WSZF, 0.0f));
    int we = (int)rintf(fminf(pb + WSZF, (float)(S - 1)));
    __shared__ float sc[MAXW], ga[MAXW], aa[MAXW];

    for (int w = warp; w < MAXW; w += 16) {
        int idx = ws + w;
        if (idx <= we) {
            int ic = min(idx, S - 1);
            const float* er = enc + ((long)ic * Bb + b) * Hh;
            const float* orow = hout + (long)b * Hh;
            float dot = 0.0f;
            for (int h = lane; h < Hh; h += 32) dot += orow[h] * er[h];
            #pragma unroll
            for (int o = 16; o > 0; o >>= 1) dot += __shfl_down_sync(0xffffffff, dot, o);
            if (lane == 0) {
                sc[w] = dot;
                ga[w] = expf(((float)idx - pb) / 50.0f);
            }
        } else if (lane == 0) {
            sc[w] = 0.0f;
            ga[w] = 0.0f;
        }
    }
    __syncthreads();
    if (tid < MAXW) {
        float m = -1e30f;
        for (int w = 0; w < MAXW; w++) m = fmaxf(m, sc[w]);
        float den = 0.0f;
        for (int w = 0; w < MAXW; w++) den += expf(sc[w] - m);
        float a = expf(sc[tid] - m) / den * ga[tid];
        aa[tid] = a;
        a_out[b * MAXW + tid] = a;
    }
    __syncthreads();
    for (int h = tid; h < Hh; h += blockDim.x) {
        float s = 0.0f;
        for (int w = 0; w < MAXW; w++) {
            int idx = ws + w;
            if (idx <= we)
                s += aa[w] * enc[((long)idx * Bb + b) * Hh + h];
        }
        g_ctx[b * Hh + h] = s;
    }
}

// ---------------------------------------------------------------------------
// Fused: merge fc2 per-slot (m,s) partials -> lse, then subtract over the row.
// grid = 128 rows, 1024 threads.
__global__ void k_ls_fin(float* __restrict__ y) {
    int row = blockIdx.x, tid = threadIdx.x;
    int lane = tid & 31, w = tid >> 5;
    __shared__ float rm[32], rs[32];
    __shared__ float s_lse;
    float m = -1e30f, s = 0.0f;
    for (int t = tid; t < NT2; t += 1024)
        msmerge(m, s, g_pm[(long)row * NT2 + t], g_ps[(long)row * NT2 + t]);
    #pragma unroll
    for (int o = 16; o > 0; o >>= 1)
        msmerge(m, s, __shfl_xor_sync(~0u, m, o), __shfl_xor_sync(~0u, s, o));
    if (lane == 0) { rm[w] = m; rs[w] = s; }
    __syncthreads();
    if (tid < 32) {
        m = rm[tid]; s = rs[tid];
        #pragma unroll
        for (int o = 16; o > 0; o >>= 1)
            msmerge(m, s, __shfl_xor_sync(~0u, m, o), __shfl_xor_sync(~0u, s, o));
        if (tid == 0) s_lse = m + logf(s);
    }
    __syncthreads();
    float lse = s_lse;
    float* yr = y + (long)row * Vv;
    for (int j = tid; j < Vv / 4; j += 1024) {
        float4 v = *(const float4*)(yr + j * 4);
        v.x -= lse; v.y -= lse; v.z -= lse; v.w -= lse;
        *(float4*)(yr + j * 4) = v;
    }
}

// ---------------------------------------------------------------------------
extern "C" void kernel_launch(void* const* d_in, const int* in_sizes, int n_in,
                              void* d_out, int out_size) {
    const float* enc  = (const float*)d_in[1];
    const int*   word = (const int*)  d_in[2];
    const float* h0   = (const float*)d_in[3];
    const float* c0   = (const float*)d_in[4];
    const float* emb  = (const float*)d_in[5];
    const float* Wih  = (const float*)d_in[6];
    const float* Whh  = (const float*)d_in[7];
    const float* bih  = (const float*)d_in[8];
    const float* bhh  = (const float*)d_in[9];
    const float* aw1  = (const float*)d_in[10];
    const float* ab1  = (const float*)d_in[11];
    const float* aw2  = (const float*)d_in[12];
    const float* ab2  = (const float*)d_in[13];
    const float* f1w  = (const float*)d_in[14];
    const float* f1b  = (const float*)d_in[15];
    const float* f2w  = (const float*)d_in[16];
    const float* f2b  = (const float*)d_in[17];

    int S = in_sizes[1] / (Bb * Hh);

    float* out = (float*)d_out;
    float* y   = out + Y_OFF;
    float* o2  = out + O2_OFF;
    float* hN  = out + H_OFF;
    float* cN  = out + C_OFF;
    float* aO  = out + A_OFF;

    const int SZ32   = 2 * (128 + 32) * 128;    // 40960
    const int SZ64G  = 2 * (128 + 64) * 128;    // 49152
    const int SZ128F = 3 * (128 + 128) * 128;   // 98304

    static float *p_g0 = nullptr, *p_g1 = nullptr, *p_ctx = nullptr,
                 *p_pm = nullptr, *p_ps = nullptr;
    static cudaStream_t s1 = nullptr;
    static cudaEvent_t e1 = nullptr, e2 = nullptr;
    static bool inited = false;
    if (!inited) {
        cudaGetSymbolAddress((void**)&p_g0,  g_gates);
        cudaGetSymbolAddress((void**)&p_g1,  g_gates2);
        cudaGetSymbolAddress((void**)&p_ctx, g_ctx);
        cudaGetSymbolAddress((void**)&p_pm,  g_pm);
        cudaGetSymbolAddress((void**)&p_ps,  g_ps);
        cudaFuncSetAttribute(k_mega_gates, cudaFuncAttributeMaxDynamicSharedMemorySize, SZ64G);
        cudaFuncSetAttribute(k_gates_x1,   cudaFuncAttributeMaxDynamicSharedMemorySize, SZ64G);
        cudaFuncSetAttribute(k_proj_sk4,   cudaFuncAttributeMaxDynamicSharedMemorySize, SZ32);
        cudaFuncSetAttribute(k_fc1_hout,   cudaFuncAttributeMaxDynamicSharedMemorySize, SZ32);
        cudaFuncSetAttribute(k_fc1_ctx,    cudaFuncAttributeMaxDynamicSharedMemorySize, SZ32);
        cudaFuncSetAttribute(k_fc2,        cudaFuncAttributeMaxDynamicSharedMemorySize, SZ128F);
        cudaStreamCreateWithFlags(&s1, cudaStreamNonBlocking);
        cudaEventCreateWithFlags(&e1, cudaEventDisableTiming);
        cudaEventCreateWithFlags(&e2, cudaEventDisableTiming);
        inited = true;
    }

    const float* h_l0 = hN;                        // layer-0 h output
    const float* hout = hN + (long)Bb * Hh;        // layer-1 h output ("out")

    // 1. mega gates: L0-x (embed fused), L0-h, L1-h — one 384-CTA launch
    k_mega_gates<<<384, 128, SZ64G>>>(emb, word,
                                      h0, Wih, Whh,
                                      h0 + (long)Bb * Hh, Whh + (long)4 * Hh * Hh,
                                      p_g0, p_g1);
    // 2. cell 0 (scalar, 512 CTAs)
    k_lstm_cell<<<Bb * Hh / 256, 256>>>(p_g0, p_g0 + 2 * (long)SLAB,
                                        bih, bhh, c0, cN, hN);
    // 3. L1-x gates (split-K4) + cell 1 (6 partial slabs, scalar)
    k_gates_x1<<<256, 128, SZ64G>>>(h_l0, Wih + (long)4 * Hh * Hh, p_g1);
    k_lstm_cell6<<<Bb * Hh / 256, 256>>>(p_g1,
                                         bih + 4 * Hh, bhh + 4 * Hh,
                                         c0 + (long)Bb * Hh,
                                         cN + (long)Bb * Hh,
                                         hN + (long)Bb * Hh);

    // --- fork: fc1 hout-half runs on side stream concurrently with attention ---
    cudaEventRecord(e1, 0);
    cudaStreamWaitEvent(s1, e1, 0);
    k_fc1_hout<<<64, 128, SZ32, s1>>>(hout, f1w, p_g0);

    // 4. attention position: proj split-K4 + fused combine/dot/sigmoid (main stream)
    k_proj_sk4<<<64, 128, SZ32>>>(hout, aw1, p_g1);
    k_attnpos<<<Bb, 128>>>(p_g1, ab1, aw2, ab2, S);

    // 5. windowed attention -> a, ctx
    k_attn_ctx<<<Bb, 512>>>(hout, enc, S, aO);

    // 6. fc1 ctx-half (main stream), then join side stream, then combine
    k_fc1_ctx<<<64, 128, SZ32>>>(p_ctx, f1w, p_g0);
    cudaEventRecord(e2, s1);
    cudaStreamWaitEvent(0, e2, 0);
    k_comb4_tanh<<<Bb * Hh / 256, 256>>>(p_g0, f1b, o2, Hh);

    // 7. fc2 (BN=128, fused softmax partials) + fused lse merge+subtract
    k_fc2<<<Vv / 128, 256, SZ128F>>>(o2, f2w, f2b, y, p_pm, p_ps);
    k_ls_fin<<<Bb, 1024>>>(y);
}

// round 17
// speedup vs baseline: 1.0394x; 1.0394x over previous
#include <cuda_runtime.h>
#include <math.h>
#include <stdint.h>

#define Bb   128
#define Hh   1024
#define HH2  512
#define Vv   32000
#define Ll   2
#define MAXW 21
#define WSZF 10.0f
#define NT2  500          // fc2 softmax partial slots (250 tiles x 2 warp-cols)

// output layout (concatenated tuple: y, o2, h_new, c_new, a)
#define Y_OFF  0
#define O2_OFF (Bb*Vv)
#define H_OFF  (O2_OFF + Bb*Hh)
#define C_OFF  (H_OFF + Ll*Bb*Hh)
#define A_OFF  (C_OFF + Ll*Bb*Hh)

#define SLAB (Bb*4*Hh)   // one gates partial slab (128 x 4096)

// scratch (device globals — no allocation allowed)
__device__ float g_gates[4*Bb*4*Hh];    // L0 slabs; later fc1 partials
__device__ float g_gates2[6*Bb*4*Hh];   // L1 slabs; later attn proj partials
__device__ float g_pb[Bb];
__device__ float g_ctx[Bb*Hh];
__device__ float g_pm[Bb*NT2];
__device__ float g_ps[Bb*NT2];

__device__ __forceinline__ float sigm(float x) { return 1.0f / (1.0f + expf(-x)); }

// ---------------------------------------------------------------------------
// async-copy / mma helpers
__device__ __forceinline__ void cp16(uint32_t dst, const float* src) {
    asm volatile("cp.async.cg.shared.global [%0], [%1], 16;"
                 :: "r"(dst), "l"(__cvta_generic_to_global(src)));
}
__device__ __forceinline__ void ldm_x4(uint32_t* r, uint32_t addr) {
    asm volatile("ldmatrix.sync.aligned.m8n8.x4.shared.b16 {%0,%1,%2,%3}, [%4];"
                 : "=r"(r[0]), "=r"(r[1]), "=r"(r[2]), "=r"(r[3]) : "r"(addr));
}
__device__ __forceinline__ void cvt_tf32(uint32_t& x) {
    asm volatile("cvt.rna.tf32.f32 %0, %0;" : "+r"(x));
}
__device__ __forceinline__ void mma_tf32(float* d, const uint32_t* a, const uint32_t* b) {
    asm volatile("mma.sync.aligned.m16n8k8.row.col.f32.tf32.tf32.f32 "
                 "{%0,%1,%2,%3}, {%4,%5,%6,%7}, {%8,%9}, {%0,%1,%2,%3};"
                 : "+f"(d[0]), "+f"(d[1]), "+f"(d[2]), "+f"(d[3])
                 : "r"(a[0]), "r"(a[1]), "r"(a[2]), "r"(a[3]),
                   "r"(b[0]), "r"(b[1]));
}

// swizzled byte offset of 16B chunk (row stride 128B, 8 chunks/row)
__device__ __forceinline__ uint32_t swz(int row, int chunk) {
    return (uint32_t)(row * 128 + ((chunk ^ (row & 7)) << 4));
}

// online (m,s) merge
__device__ __forceinline__ void msmerge(float& m, float& s, float om, float os) {
    float nm = fmaxf(m, om);
    s = s * __expf(m - nm) + os * __expf(om - nm);
    m = nm;
}

// ---------------------------------------------------------------------------
// Stage a K-chunk of 32 fp32 cols: A[128 rows] (optionally word-indirect rows),
// W[BN rows] -> swizzled SMEM.
template<int BN, int NW>
__device__ __forceinline__ void g_load(
    uint32_t abase, const float* __restrict__ A, const int* __restrict__ word,
    const float* __restrict__ W, int ldA, int ldW, int kOff,
    int kb, int n0, int tid)
{
    constexpr int THREADS = NW * 32;
    uint32_t bbase = abase + 128 * 128;
    #pragma unroll
    for (int i = 0; i < 1024 / THREADS; i++) {          // A: 128 rows x 8 chunks
        int idx = tid + i * THREADS;
        int r = idx >> 3, c = idx & 7;
        long rowoff = word ? (long)word[r] * ldA : (long)r * ldA;
        cp16(abase + swz(r, c), A + rowoff + kOff + kb + c * 4);
    }
    #pragma unroll
    for (int i = 0; i < BN * 8 / THREADS; i++) {        // B: BN rows x 8 chunks
        int idx = tid + i * THREADS;
        int r = idx >> 3, c = idx & 7;
        cp16(bbase + swz(r, c), W + (long)(n0 + r) * ldW + kb + c * 4);
    }
}

// ---------------------------------------------------------------------------
// Core tf32 mma GEMM. ACT: 0 = bias, 1 = bias+tanh, 2 = raw.
// SMX: emit per-row (max, sumexp) partials for fused log-softmax
// (slot = tile + wn so multiple N-warps don't collide).
template<int BN, int NW, int WN, int NST, int ACT, int SMX>
__device__ __forceinline__ void gemm_core(
    const float* __restrict__ A, const int* __restrict__ word,
    const float* __restrict__ W, int ldA, int ldW, int kOff, int kLen,
    const float* __restrict__ bias, float* __restrict__ C, int N, int n0, char* sm,
    float* __restrict__ Pm, float* __restrict__ Ps, int tile, int nTiles)
{
    constexpr int STAGE = (128 + BN) * 128;
    constexpr int WARPN = BN / WN, NT = WARPN / 8;
    constexpr int WM = NW / WN, WTM = 128 / WM, MT = WTM / 16;

    uint32_t smb = (uint32_t)__cvta_generic_to_shared(sm);
    int tid = threadIdx.x, lane = tid & 31, w = tid >> 5;
    int wm = w / WN, wn = w % WN;
    int NITER = kLen / 32;

    float acc[MT][NT][4] = {};

    #pragma unroll
    for (int s = 0; s < NST; s++) {
        if (s < NITER)
            g_load<BN, NW>(smb + s * STAGE, A, word, W, ldA, ldW, kOff, s * 32, n0, tid);
        asm volatile("cp.async.commit_group;" ::: "memory");
    }

    int a_lrow = lane & 15, a_lsel = lane >> 4;
    int b_lrow = (lane & 7) + ((lane >> 4) << 3);
    int b_lsel = (lane >> 3) & 1;

    for (int it = 0; it < NITER; it++) {
        asm volatile("cp.async.wait_group %0;" :: "n"(NST - 1) : "memory");
        __syncthreads();

        uint32_t abase = smb + (it % NST) * STAGE;
        uint32_t bbase = abase + 128 * 128;
        #pragma unroll
        for (int ks = 0; ks < 4; ks++) {
            int cb = 2 * ks;
            uint32_t a[MT][4], b[NT][2];
            #pragma unroll
            for (int mt = 0; mt < MT; mt++) {
                int row = wm * WTM + mt * 16 + a_lrow;
                ldm_x4(a[mt], abase + (uint32_t)(row * 128 +
                       (((cb + a_lsel) ^ (a_lrow & 7)) << 4)));
            }
            #pragma unroll
            for (int j = 0; j < NT / 2; j++) {
                int row = wn * WARPN + j * 16 + b_lrow;
                uint32_t r4[4];
                ldm_x4(r4, bbase + (uint32_t)(row * 128 +
                       (((cb + b_lsel) ^ (b_lrow & 7)) << 4)));
                b[j*2][0] = r4[0]; b[j*2][1] = r4[1];
                b[j*2+1][0] = r4[2]; b[j*2+1][1] = r4[3];
            }
            #pragma unroll
            for (int mt = 0; mt < MT; mt++)
                #pragma unroll
                for (int q = 0; q < 4; q++) cvt_tf32(a[mt][q]);
            #pragma unroll
            for (int nt = 0; nt < NT; nt++) { cvt_tf32(b[nt][0]); cvt_tf32(b[nt][1]); }
            #pragma unroll
            for (int mt = 0; mt < MT; mt++)
                #pragma unroll
                for (int nt = 0; nt < NT; nt++)
                    mma_tf32(acc[mt][nt], a[mt], b[nt]);
        }
        __syncthreads();
        if (it + NST < NITER)
            g_load<BN, NW>(smb + (it % NST) * STAGE, A, word, W, ldA, ldW, kOff,
                           (it + NST) * 32, n0, tid);
        asm volatile("cp.async.commit_group;" ::: "memory");
    }

    // epilogue
    #pragma unroll
    for (int mt = 0; mt < MT; mt++) {
        int mrow = wm * WTM + mt * 16 + (lane >> 2);
        float em0 = -1e30f, es0 = 0.0f, em1 = -1e30f, es1 = 0.0f;
        #pragma unroll
        for (int nt = 0; nt < NT; nt++) {
            int n = n0 + wn * WARPN + nt * 8 + (lane & 3) * 2;
            float b0a = 0.0f, b0b = 0.0f;
            if (ACT != 2) { b0a = bias[n]; b0b = bias[n + 1]; }
            float v0 = acc[mt][nt][0] + b0a;
            float v1 = acc[mt][nt][1] + b0b;
            float v2 = acc[mt][nt][2] + b0a;
            float v3 = acc[mt][nt][3] + b0b;
            if (ACT == 1) { v0 = tanhf(v0); v1 = tanhf(v1); v2 = tanhf(v2); v3 = tanhf(v3); }
            if (SMX) {
                float nm = fmaxf(em0, fmaxf(v0, v1));
                es0 = es0 * __expf(em0 - nm) + __expf(v0 - nm) + __expf(v1 - nm);
                em0 = nm;
                nm = fmaxf(em1, fmaxf(v2, v3));
                es1 = es1 * __expf(em1 - nm) + __expf(v2 - nm) + __expf(v3 - nm);
                em1 = nm;
            }
            *(float2*)(C + (long)mrow * N + n)       = make_float2(v0, v1);
            *(float2*)(C + (long)(mrow + 8) * N + n) = make_float2(v2, v3);
        }
        if (SMX) {
            #pragma unroll
            for (int o = 1; o <= 2; o <<= 1) {
                msmerge(em0, es0, __shfl_xor_sync(~0u, em0, o), __shfl_xor_sync(~0u, es0, o));
                msmerge(em1, es1, __shfl_xor_sync(~0u, em1, o), __shfl_xor_sync(~0u, es1, o));
            }
            if ((lane & 3) == 0) {
                int slot = tile + wn;
                Pm[(long)mrow * nTiles + slot]       = em0;
                Ps[(long)mrow * nTiles + slot]       = es0;
                Pm[(long)(mrow + 8) * nTiles + slot] = em1;
                Ps[(long)(mrow + 8) * nTiles + slot] = es1;
            }
        }
    }
}

// ---------------------------------------------------------------------------
// Mega gates: job0 = emb[word]@Wih0 (sk2), job1 = h0[0]@Whh0 (sk2),
// job2 = h0[1]@Whh1 (sk2). BN=64. grid = 384.
__global__ void __launch_bounds__(128, 4) k_mega_gates(
    const float* __restrict__ emb, const int* __restrict__ word,
    const float* __restrict__ h00, const float* __restrict__ Wih0,
    const float* __restrict__ Whh0,
    const float* __restrict__ h01, const float* __restrict__ Whh1,
    float* __restrict__ G0, float* __restrict__ G1)
{
    extern __shared__ char sm[];
    int job = blockIdx.x >> 7;
    int r = blockIdx.x & 127;
    int tile = r >> 1, ks = r & 1;
    const float* A; const int* wd = nullptr; const float* W; float* C; int kOff = 0;
    if (job == 0)      { A = emb;             wd = word; kOff = ks * 512;
                         W = Wih0 + ks * 512; C = G0 + (long)ks * SLAB; }
    else if (job == 1) { A = h00 + ks * 512;  W = Whh0 + ks * 512;
                         C = G0 + (long)(2 + ks) * SLAB; }
    else               { A = h01 + ks * 512;  W = Whh1 + ks * 512;
                         C = G1 + (long)ks * SLAB; }
    gemm_core<64, 4, 1, 2, 2, 0>(A, wd, W, Hh, Hh, kOff, 512, nullptr,
                                 C, 4 * Hh, tile * 64, sm, nullptr, nullptr, 0, 0);
}

// Layer-1 x-part: h_l0 @ Wih1 (split-K4). BN=64. grid = 256.
__global__ void __launch_bounds__(128, 4) k_gates_x1(
    const float* __restrict__ hl0, const float* __restrict__ Wih1,
    float* __restrict__ G1)
{
    extern __shared__ char sm[];
    int tile = blockIdx.x >> 2, ks = blockIdx.x & 3;
    gemm_core<64, 4, 1, 2, 2, 0>(hl0 + ks * 256, nullptr, Wih1 + ks * 256,
                                 Hh, Hh, 0, 256, nullptr,
                                 G1 + (long)(2 + ks) * SLAB, 4 * Hh, tile * 64, sm,
                                 nullptr, nullptr, 0, 0);
}

// attn proj split-K=4 (K quarters of 256). BN=32, NST=3. grid = 64.
__global__ void __launch_bounds__(128, 3) k_proj_sk4(
    const float* __restrict__ hout, const float* __restrict__ aw1,
    float* __restrict__ P)
{
    extern __shared__ char sm[];
    int ks = blockIdx.x & 3, tile = blockIdx.x >> 2;
    gemm_core<32, 4, 1, 3, 2, 0>(hout + ks * 256, nullptr, aw1 + ks * 256,
                                 Hh, Hh, 0, 256, nullptr,
                                 P + (long)ks * 128 * HH2, HH2, tile * 32, sm,
                                 nullptr, nullptr, 0, 0);
}

// fc1 split-K=4 over cat=[ctx|hout]: quarters 0,1 from ctx, 2,3 from hout.
// BN=32, NST=3. grid = 128.
__global__ void __launch_bounds__(128, 3) k_fc1_sk4(
    const float* __restrict__ ctx, const float* __restrict__ hout,
    const float* __restrict__ f1w, float* __restrict__ P)
{
    extern __shared__ char sm[];
    int ks = blockIdx.x & 3, tile = blockIdx.x >> 2;
    const float* A = (ks < 2) ? (ctx + ks * 512) : (hout + (ks - 2) * 512);
    gemm_core<32, 4, 1, 3, 2, 0>(A, nullptr, f1w + ks * 512,
                                 Hh, 2 * Hh, 0, 512, nullptr,
                                 P + (long)ks * 128 * Hh, Hh, tile * 32, sm,
                                 nullptr, nullptr, 0, 0);
}

// fc2: BN=128, 256 threads, WN=2, NST=3, fused softmax partials. grid = 250.
__global__ void __launch_bounds__(256, 2) k_fc2(
    const float* __restrict__ o2, const float* __restrict__ f2w,
    const float* __restrict__ f2b, float* __restrict__ y,
    float* __restrict__ Pm, float* __restrict__ Ps)
{
    extern __shared__ char sm[];
    gemm_core<128, 8, 2, 3, 0, 1>(o2, nullptr, f2w, Hh, Hh, 0, Hh, f2b,
                                  y, Vv, blockIdx.x * 128, sm, Pm, Ps,
                                  blockIdx.x * 2, NT2);
}

// ---------------------------------------------------------------------------
// LSTM cell 0 (scalar): gates = x-ks0 + x-ks1 + h-ks0 + h-ks1 + bih + bhh
__global__ void k_lstm_cell(const float* __restrict__ p0, const float* __restrict__ p1,
                            const float* __restrict__ bi, const float* __restrict__ bh,
                            const float* __restrict__ c_prev,
                            float* __restrict__ c_out, float* __restrict__ h_out) {
    int i = blockIdx.x * 256 + threadIdx.x;   // B*H
    int b = i >> 10, h = i & 1023;
    long base = (long)b * 4 * Hh + h;
    float gate[4];
    #pragma unroll
    for (int gi = 0; gi < 4; gi++) {
        long off = base + gi * Hh;
        gate[gi] = p0[off] + p0[SLAB + off] + p1[off] + p1[SLAB + off]
                 + bi[gi * Hh + h] + bh[gi * Hh + h];
    }
    float cp = c_prev[i];
    float c = sigm(gate[1]) * cp + sigm(gate[0]) * tanhf(gate[2]);
    c_out[i] = c;
    h_out[i] = sigm(gate[3]) * tanhf(c);
}

// LSTM cell 1 (scalar): gates = sum of 6 slabs + bih + bhh
__global__ void k_lstm_cell6(const float* __restrict__ P,
                             const float* __restrict__ bi, const float* __restrict__ bh,
                             const float* __restrict__ c_prev,
                             float* __restrict__ c_out, float* __restrict__ h_out) {
    int i = blockIdx.x * 256 + threadIdx.x;   // B*H
    int b = i >> 10, h = i & 1023;
    long base = (long)b * 4 * Hh + h;
    float gate[4];
    #pragma unroll
    for (int gi = 0; gi < 4; gi++) {
        long off = base + gi * Hh;
        float v = P[off];
        #pragma unroll
        for (int sl = 1; sl < 6; sl++) v += P[(long)sl * SLAB + off];
        gate[gi] = v + bi[gi * Hh + h] + bh[gi * Hh + h];
    }
    float cp = c_prev[i];
    float c = sigm(gate[1]) * cp + sigm(gate[0]) * tanhf(gate[2]);
    c_out[i] = c;
    h_out[i] = sigm(gate[3]) * tanhf(c);
}

// ---------------------------------------------------------------------------
// 4-partial combine with tanh (fc1), scalar
__global__ void k_comb4_tanh(const float* __restrict__ P, const float* __restrict__ bias,
                             float* __restrict__ out, int N) {
    int i = blockIdx.x * 256 + threadIdx.x;   // over 128*N
    long s = (long)128 * N;
    int h = i % N;
    out[i] = tanhf(P[i] + P[s + i] + P[2 * s + i] + P[3 * s + i] + bias[h]);
}

// ---------------------------------------------------------------------------
// Fused attn position: combine 4 proj partials + bias, tanh, dot w2, sigmoid -> pb
__global__ void k_attnpos(const float* __restrict__ P, const float* __restrict__ ab1,
                          const float* __restrict__ w2, const float* __restrict__ b2,
                          int S) {
    int b = blockIdx.x, tid = threadIdx.x;
    long s = (long)128 * HH2;
    long row = (long)b * HH2;
    __shared__ float red[4];
    float acc = 0.0f;
    #pragma unroll
    for (int jj = 0; jj < HH2 / 128; jj++) {
        int j = tid + jj * 128;
        float v = P[row + j] + P[s + row + j] + P[2 * s + row + j] + P[3 * s + row + j]
                + ab1[j];
        acc += tanhf(v) * w2[j];
    }
    #pragma unroll
    for (int o = 16; o > 0; o >>= 1) acc += __shfl_xor_sync(~0u, acc, o);
    if ((tid & 31) == 0) red[tid >> 5] = acc;
    __syncthreads();
    if (tid == 0)
        g_pb[b] = (float)S * sigm(red[0] + red[1] + red[2] + red[3] + b2[0]);
}

// ---------------------------------------------------------------------------
// Windowed attention (512 threads): scores, softmax*gauss, a, ctx
__global__ void k_attn_ctx(const float* __restrict__ hout, const float* __restrict__ enc,
                           int S, float* __restrict__ a_out) {
    int b = blockIdx.x, tid = threadIdx.x;
    int warp = tid >> 5, lane = tid & 31;
    float pb = g_pb[b];
    int ws = (int)rintf(fmaxf(pb - WSZF, 0.0f));
    int we = (int)rintf(fminf(pb + WSZF, (float)(S - 1)));
    __shared__ float sc[MAXW], ga[MAXW], aa[MAXW];

    for (int w = warp; w < MAXW; w += 16) {
        int idx = ws + w;
        if (idx <= we) {
            int ic = min(idx, S - 1);
            const float* er = enc + ((long)ic * Bb + b) * Hh;
            const float* orow = hout + (long)b * Hh;
            float dot = 0.0f;
            for (int h = lane; h < Hh; h += 32) dot += orow[h] * er[h];
            #pragma unroll
            for (int o = 16; o > 0; o >>= 1) dot += __shfl_down_sync(0xffffffff, dot, o);
            if (lane == 0) {
                sc[w] = dot;
                ga[w] = expf(((float)idx - pb) / 50.0f);
            }
        } else if (lane == 0) {
            sc[w] = 0.0f;
            ga[w] = 0.0f;
        }
    }
    __syncthreads();
    if (tid < MAXW) {
        float m = -1e30f;
        for (int w = 0; w < MAXW; w++) m = fmaxf(m, sc[w]);
        float den = 0.0f;
        for (int w = 0; w < MAXW; w++) den += expf(sc[w] - m);
        float a = expf(sc[tid] - m) / den * ga[tid];
        aa[tid] = a;
        a_out[b * MAXW + tid] = a;
    }
    __syncthreads();
    for (int h = tid; h < Hh; h += blockDim.x) {
        float s = 0.0f;
        for (int w = 0; w < MAXW; w++) {
            int idx = ws + w;
            if (idx <= we)
                s += aa[w] * enc[((long)idx * Bb + b) * Hh + h];
        }
        g_ctx[b * Hh + h] = s;
    }
}

// ---------------------------------------------------------------------------
// Fused: merge fc2 per-slot (m,s) partials -> lse, then subtract over the row.
// grid = 128 rows, 1024 threads.
__global__ void k_ls_fin(float* __restrict__ y) {
    int row = blockIdx.x, tid = threadIdx.x;
    int lane = tid & 31, w = tid >> 5;
    __shared__ float rm[32], rs[32];
    __shared__ float s_lse;
    float m = -1e30f, s = 0.0f;
    for (int t = tid; t < NT2; t += 1024)
        msmerge(m, s, g_pm[(long)row * NT2 + t], g_ps[(long)row * NT2 + t]);
    #pragma unroll
    for (int o = 16; o > 0; o >>= 1)
        msmerge(m, s, __shfl_xor_sync(~0u, m, o), __shfl_xor_sync(~0u, s, o));
    if (lane == 0) { rm[w] = m; rs[w] = s; }
    __syncthreads();
    if (tid < 32) {
        m = rm[tid]; s = rs[tid];
        #pragma unroll
        for (int o = 16; o > 0; o >>= 1)
            msmerge(m, s, __shfl_xor_sync(~0u, m, o), __shfl_xor_sync(~0u, s, o));
        if (tid == 0) s_lse = m + logf(s);
    }
    __syncthreads();
    float lse = s_lse;
    float* yr = y + (long)row * Vv;
    for (int j = tid; j < Vv / 4; j += 1024) {
        float4 v = *(const float4*)(yr + j * 4);
        v.x -= lse; v.y -= lse; v.z -= lse; v.w -= lse;
        *(float4*)(yr + j * 4) = v;
    }
}

// ---------------------------------------------------------------------------
extern "C" void kernel_launch(void* const* d_in, const int* in_sizes, int n_in,
                              void* d_out, int out_size) {
    const float* enc  = (const float*)d_in[1];
    const int*   word = (const int*)  d_in[2];
    const float* h0   = (const float*)d_in[3];
    const float* c0   = (const float*)d_in[4];
    const float* emb  = (const float*)d_in[5];
    const float* Wih  = (const float*)d_in[6];
    const float* Whh  = (const float*)d_in[7];
    const float* bih  = (const float*)d_in[8];
    const float* bhh  = (const float*)d_in[9];
    const float* aw1  = (const float*)d_in[10];
    const float* ab1  = (const float*)d_in[11];
    const float* aw2  = (const float*)d_in[12];
    const float* ab2  = (const float*)d_in[13];
    const float* f1w  = (const float*)d_in[14];
    const float* f1b  = (const float*)d_in[15];
    const float* f2w  = (const float*)d_in[16];
    const float* f2b  = (const float*)d_in[17];

    int S = in_sizes[1] / (Bb * Hh);

    float* out = (float*)d_out;
    float* y   = out + Y_OFF;
    float* o2  = out + O2_OFF;
    float* hN  = out + H_OFF;
    float* cN  = out + C_OFF;
    float* aO  = out + A_OFF;

    const int SZ32_3 = 3 * (128 + 32) * 128;    // 61440
    const int SZ64G  = 2 * (128 + 64) * 128;    // 49152
    const int SZ128F = 3 * (128 + 128) * 128;   // 98304

    static float *p_g0 = nullptr, *p_g1 = nullptr, *p_ctx = nullptr,
                 *p_pm = nullptr, *p_ps = nullptr;
    static bool inited = false;
    if (!inited) {
        cudaGetSymbolAddress((void**)&p_g0,  g_gates);
        cudaGetSymbolAddress((void**)&p_g1,  g_gates2);
        cudaGetSymbolAddress((void**)&p_ctx, g_ctx);
        cudaGetSymbolAddress((void**)&p_pm,  g_pm);
        cudaGetSymbolAddress((void**)&p_ps,  g_ps);
        cudaFuncSetAttribute(k_mega_gates, cudaFuncAttributeMaxDynamicSharedMemorySize, SZ64G);
        cudaFuncSetAttribute(k_gates_x1,   cudaFuncAttributeMaxDynamicSharedMemorySize, SZ64G);
        cudaFuncSetAttribute(k_proj_sk4,   cudaFuncAttributeMaxDynamicSharedMemorySize, SZ32_3);
        cudaFuncSetAttribute(k_fc1_sk4,    cudaFuncAttributeMaxDynamicSharedMemorySize, SZ32_3);
        cudaFuncSetAttribute(k_fc2,        cudaFuncAttributeMaxDynamicSharedMemorySize, SZ128F);
        inited = true;
    }

    const float* h_l0 = hN;                        // layer-0 h output
    const float* hout = hN + (long)Bb * Hh;        // layer-1 h output ("out")

    // 1. mega gates: L0-x (embed fused), L0-h, L1-h — one 384-CTA launch
    k_mega_gates<<<384, 128, SZ64G>>>(emb, word,
                                      h0, Wih, Whh,
                                      h0 + (long)Bb * Hh, Whh + (long)4 * Hh * Hh,
                                      p_g0, p_g1);
    // 2. cell 0 (scalar, 512 CTAs)
    k_lstm_cell<<<Bb * Hh / 256, 256>>>(p_g0, p_g0 + 2 * (long)SLAB,
                                        bih, bhh, c0, cN, hN);
    // 3. L1-x gates (split-K4) + cell 1 (6 partial slabs, scalar)
    k_gates_x1<<<256, 128, SZ64G>>>(h_l0, Wih + (long)4 * Hh * Hh, p_g1);
    k_lstm_cell6<<<Bb * Hh / 256, 256>>>(p_g1,
                                         bih + 4 * Hh, bhh + 4 * Hh,
                                         c0 + (long)Bb * Hh,
                                         cN + (long)Bb * Hh,
                                         hN + (long)Bb * Hh);

    // 4. attention position: proj split-K4 (NST=3) + fused combine/dot/sigmoid
    k_proj_sk4<<<64, 128, SZ32_3>>>(hout, aw1, p_g1);
    k_attnpos<<<Bb, 128>>>(p_g1, ab1, aw2, ab2, S);

    // 5. windowed attention -> a, ctx
    k_attn_ctx<<<Bb, 512>>>(hout, enc, S, aO);

    // 6. fc1 split-K4 (NST=3) over [ctx|hout] + tanh-combine (scalar) -> o2
    k_fc1_sk4<<<128, 128, SZ32_3>>>(p_ctx, hout, f1w, p_g0);
    k_comb4_tanh<<<Bb * Hh / 256, 256>>>(p_g0, f1b, o2, Hh);

    // 7. fc2 (BN=128, fused softmax partials) + fused lse merge+subtract
    k_fc2<<<Vv / 128, 256, SZ128F>>>(o2, f2w, f2b, y, p_pm, p_ps);
    k_ls_fin<<<Bb, 1024>>>(y);
}